// round 1
// baseline (speedup 1.0000x reference)
#include <cuda_runtime.h>
#include <cstddef>

// Problem constants
#define BATCH   4
#define S_LEN   2048
#define D_MODEL 1024
#define NHEAD   16
#define HEAD_D  64
#define TDQ     (3 * D_MODEL)          // 3072
#define M_ROWS  (BATCH * S_LEN)        // 8192

// Scratch (allocation-free rule: __device__ globals)
__device__ float g_qkv [(size_t)M_ROWS * TDQ];      // [B*S, 3D]
__device__ float g_attn[(size_t)M_ROWS * D_MODEL];  // [B*S, D]

// ---------------------------------------------------------------------------
// SGEMM (NT): C[m,n] = sum_k A[m,k] * B[n,k] + bias[n]
// A: [M,K] row-major, B: [N,K] row-major. All dims multiples of 128 (K mult 8).
// 128x128 block tile, BK=8, 256 threads, 8x8 micro-tile per thread.
// ---------------------------------------------------------------------------
__global__ void __launch_bounds__(256, 2)
sgemm_nt_bias(const float* __restrict__ A, const float* __restrict__ B,
              const float* __restrict__ bias, float* __restrict__ C,
              int M, int N, int K)
{
    __shared__ float As[8][128];
    __shared__ float Bs[8][128];

    const int tid = threadIdx.x;
    const int tx  = tid & 15;          // 16 x 16 thread grid
    const int ty  = tid >> 4;
    const int row0 = blockIdx.y * 128;
    const int col0 = blockIdx.x * 128;

    // one float4 of A and B per thread per k-tile
    const int lr = tid >> 1;           // 0..127 tile row
    const int lc = (tid & 1) * 4;      // 0 or 4 tile col

    const float* Ap = A + (size_t)(row0 + lr) * K + lc;
    const float* Bp = B + (size_t)(col0 + lr) * K + lc;

    float acc[8][8];
    #pragma unroll
    for (int i = 0; i < 8; i++)
        #pragma unroll
        for (int j = 0; j < 8; j++) acc[i][j] = 0.f;

    for (int k0 = 0; k0 < K; k0 += 8) {
        float4 a4 = *(const float4*)(Ap + k0);
        float4 b4 = *(const float4*)(Bp + k0);
        As[lc + 0][lr] = a4.x; As[lc + 1][lr] = a4.y;
        As[lc + 2][lr] = a4.z; As[lc + 3][lr] = a4.w;
        Bs[lc + 0][lr] = b4.x; Bs[lc + 1][lr] = b4.y;
        Bs[lc + 2][lr] = b4.z; Bs[lc + 3][lr] = b4.w;
        __syncthreads();

        #pragma unroll
        for (int k = 0; k < 8; k++) {
            float4 ra0 = *(const float4*)&As[k][ty * 8];
            float4 ra1 = *(const float4*)&As[k][ty * 8 + 4];
            float4 rb0 = *(const float4*)&Bs[k][tx * 8];
            float4 rb1 = *(const float4*)&Bs[k][tx * 8 + 4];
            float ra[8] = {ra0.x, ra0.y, ra0.z, ra0.w, ra1.x, ra1.y, ra1.z, ra1.w};
            float rb[8] = {rb0.x, rb0.y, rb0.z, rb0.w, rb1.x, rb1.y, rb1.z, rb1.w};
            #pragma unroll
            for (int i = 0; i < 8; i++)
                #pragma unroll
                for (int j = 0; j < 8; j++)
                    acc[i][j] += ra[i] * rb[j];
        }
        __syncthreads();
    }

    #pragma unroll
    for (int i = 0; i < 8; i++) {
        const int r = row0 + ty * 8 + i;
        float* crow = C + (size_t)r * N + col0 + tx * 8;
        const float* brow = bias + col0 + tx * 8;
        #pragma unroll
        for (int j = 0; j < 8; j++)
            crow[j] = acc[i][j] + brow[j];
    }
}

// ---------------------------------------------------------------------------
// Flash attention, fp32. One thread per query row (q and o rows in registers).
// Block: 128 threads = 128 queries. K-tile = 32 keys, K/V tiles in smem.
// grid.x = S/128 (q tiles), grid.y = B*NHEAD.
// qkv row layout per token: head h occupies cols [h*192, h*192+192) = q|k|v.
// out: [B*S, D_MODEL] with head h at cols [h*64, h*64+64).
// ---------------------------------------------------------------------------
__global__ void __launch_bounds__(128, 1)
attn_kernel(const float* __restrict__ qkv, float* __restrict__ out)
{
    __shared__ float Ks[32][HEAD_D];
    __shared__ float Vs[32][HEAD_D];

    const int tid = threadIdx.x;
    const int h   = blockIdx.y & (NHEAD - 1);
    const int b   = blockIdx.y >> 4;
    const int qrow = blockIdx.x * 128 + tid;
    const int hofs = h * 3 * HEAD_D;

    // load q row (pre-scaled by 1/sqrt(d))
    float q[HEAD_D];
    {
        const float4* qp = (const float4*)(qkv + ((size_t)(b * S_LEN + qrow)) * TDQ + hofs);
        #pragma unroll
        for (int j = 0; j < 16; j++) {
            float4 t = qp[j];
            q[4*j+0] = t.x * 0.125f; q[4*j+1] = t.y * 0.125f;
            q[4*j+2] = t.z * 0.125f; q[4*j+3] = t.w * 0.125f;
        }
    }

    float o[HEAD_D];
    #pragma unroll
    for (int j = 0; j < HEAD_D; j++) o[j] = 0.f;
    float m = -1e30f, l = 0.f;

    for (int kt = 0; kt < S_LEN; kt += 32) {
        // cooperative load of K/V tiles: 32 rows x 64 cols each
        #pragma unroll
        for (int it = 0; it < 4; it++) {
            int fid = tid + it * 128;          // float4 id, 0..511
            int r = fid >> 4;
            int c = (fid & 15) * 4;
            const float* src = qkv + ((size_t)(b * S_LEN + kt + r)) * TDQ + hofs;
            *(float4*)&Ks[r][c] = *(const float4*)(src + HEAD_D + c);
            *(float4*)&Vs[r][c] = *(const float4*)(src + 2 * HEAD_D + c);
        }
        __syncthreads();

        // scores for 32 keys (all in registers)
        float p[32];
        float mt = -1e30f;
        #pragma unroll
        for (int kk = 0; kk < 32; kk++) {
            float s = 0.f;
            #pragma unroll
            for (int j = 0; j < HEAD_D; j++) s += q[j] * Ks[kk][j];
            p[kk] = s;
            mt = fmaxf(mt, s);
        }

        const float mnew  = fmaxf(m, mt);
        const float alpha = __expf(m - mnew);
        float ls = 0.f;
        #pragma unroll
        for (int kk = 0; kk < 32; kk++) {
            p[kk] = __expf(p[kk] - mnew);
            ls += p[kk];
        }
        l = l * alpha + ls;
        m = mnew;

        #pragma unroll
        for (int j = 0; j < HEAD_D; j++) o[j] *= alpha;

        #pragma unroll
        for (int kk = 0; kk < 32; kk++) {
            const float pk = p[kk];
            #pragma unroll
            for (int j = 0; j < HEAD_D; j++) o[j] += pk * Vs[kk][j];
        }
        __syncthreads();
    }

    const float inv = 1.f / l;
    float* dst = out + ((size_t)(b * S_LEN + qrow)) * D_MODEL + h * HEAD_D;
    #pragma unroll
    for (int j = 0; j < 16; j++) {
        float4 t = make_float4(o[4*j+0] * inv, o[4*j+1] * inv,
                               o[4*j+2] * inv, o[4*j+3] * inv);
        ((float4*)dst)[j] = t;
    }
}

// ---------------------------------------------------------------------------
extern "C" void kernel_launch(void* const* d_in, const int* in_sizes, int n_in,
                              void* d_out, int out_size)
{
    const float* x     = (const float*)d_in[0];  // [4,2048,1024]
    const float* w_qkv = (const float*)d_in[1];  // [3072,1024]
    const float* b_qkv = (const float*)d_in[2];  // [3072]
    const float* w_o   = (const float*)d_in[3];  // [1024,1024]
    const float* b_o   = (const float*)d_in[4];  // [1024]
    float* out = (float*)d_out;                  // [4,2048,1024]

    float* qkv;  cudaGetSymbolAddress((void**)&qkv,  g_qkv);
    float* attn; cudaGetSymbolAddress((void**)&attn, g_attn);

    // 1) QKV projection: [8192,3072] = x[8192,1024] @ w_qkv^T + b_qkv
    {
        dim3 grid(TDQ / 128, M_ROWS / 128);
        sgemm_nt_bias<<<grid, 256>>>(x, w_qkv, b_qkv, qkv, M_ROWS, TDQ, D_MODEL);
    }

    // 2) multi-head attention -> attn [8192,1024]
    {
        dim3 grid(S_LEN / 128, BATCH * NHEAD);
        attn_kernel<<<grid, 128>>>(qkv, attn);
    }

    // 3) output projection: out = attn @ w_o^T + b_o
    {
        dim3 grid(D_MODEL / 128, M_ROWS / 128);
        sgemm_nt_bias<<<grid, 256>>>(attn, w_o, b_o, out, M_ROWS, D_MODEL, D_MODEL);
    }
}

// round 3
// speedup vs baseline: 1.6101x; 1.6101x over previous
#include <cuda_runtime.h>
#include <cuda_bf16.h>
#include <cstdint>
#include <cstddef>

// Problem constants
#define BATCH   4
#define S_LEN   2048
#define D_MODEL 1024
#define NHEAD   16
#define HEAD_D  64
#define TDQ     (3 * D_MODEL)          // 3072
#define M_ROWS  (BATCH * S_LEN)        // 8192
#define KDIM    D_MODEL                // 1024

// ---------------------------------------------------------------------------
// Scratch (__device__ globals; allocation-free rule). 16B-aligned for cp.async.
// ---------------------------------------------------------------------------
__device__ __align__(128) float         g_qkv   [(size_t)M_ROWS * TDQ];
__device__ __align__(128) __nv_bfloat16 g_x_hi  [(size_t)M_ROWS * KDIM];
__device__ __align__(128) __nv_bfloat16 g_x_lo  [(size_t)M_ROWS * KDIM];
__device__ __align__(128) __nv_bfloat16 g_wq_hi [(size_t)TDQ    * KDIM];
__device__ __align__(128) __nv_bfloat16 g_wq_lo [(size_t)TDQ    * KDIM];
__device__ __align__(128) __nv_bfloat16 g_wo_hi [(size_t)D_MODEL* KDIM];
__device__ __align__(128) __nv_bfloat16 g_wo_lo [(size_t)D_MODEL* KDIM];
__device__ __align__(128) __nv_bfloat16 g_at_hi [(size_t)M_ROWS * D_MODEL];
__device__ __align__(128) __nv_bfloat16 g_at_lo [(size_t)M_ROWS * D_MODEL];

// ---------------------------------------------------------------------------
// Helpers
// ---------------------------------------------------------------------------
__device__ __forceinline__ uint32_t smem_u32(const void* p) {
    uint32_t a;
    asm("{ .reg .u64 t; cvta.to.shared.u64 t, %1; cvt.u32.u64 %0, t; }"
        : "=r"(a) : "l"(p));
    return a;
}

#define CP_ASYNC16(saddr, gptr) \
    asm volatile("cp.async.cg.shared.global [%0], [%1], 16;" :: "r"(saddr), "l"(gptr))
#define CP_COMMIT() asm volatile("cp.async.commit_group;" ::: "memory")
#define CP_WAIT0()  asm volatile("cp.async.wait_group 0;" ::: "memory")

__device__ __forceinline__ void ldsm4(uint32_t* r, uint32_t addr) {
    asm volatile("ldmatrix.sync.aligned.m8n8.x4.shared.b16 {%0,%1,%2,%3}, [%4];"
                 : "=r"(r[0]), "=r"(r[1]), "=r"(r[2]), "=r"(r[3]) : "r"(addr));
}
__device__ __forceinline__ void ldsm2(uint32_t* r, uint32_t addr) {
    asm volatile("ldmatrix.sync.aligned.m8n8.x2.shared.b16 {%0,%1}, [%2];"
                 : "=r"(r[0]), "=r"(r[1]) : "r"(addr));
}
__device__ __forceinline__ void mma16816(float* d, const uint32_t* a, const uint32_t* b) {
    asm volatile(
        "mma.sync.aligned.m16n8k16.row.col.f32.bf16.bf16.f32 "
        "{%0,%1,%2,%3}, {%4,%5,%6,%7}, {%8,%9}, {%0,%1,%2,%3};"
        : "+f"(d[0]), "+f"(d[1]), "+f"(d[2]), "+f"(d[3])
        : "r"(a[0]), "r"(a[1]), "r"(a[2]), "r"(a[3]), "r"(b[0]), "r"(b[1]));
}

// packed fp32x2 (Blackwell FFMA2 path; base ISA on sm_100+)
__device__ __forceinline__ uint64_t pack2(float lo, float hi) {
    uint64_t r; asm("mov.b64 %0, {%1, %2};" : "=l"(r) : "f"(lo), "f"(hi)); return r;
}
__device__ __forceinline__ void unpack2(uint64_t v, float& lo, float& hi) {
    asm("mov.b64 {%0, %1}, %2;" : "=f"(lo), "=f"(hi) : "l"(v));
}
__device__ __forceinline__ uint64_t fma2(uint64_t a, uint64_t b, uint64_t c) {
    uint64_t d; asm("fma.rn.f32x2 %0, %1, %2, %3;" : "=l"(d) : "l"(a), "l"(b), "l"(c));
    return d;
}
__device__ __forceinline__ uint64_t mul2(uint64_t a, uint64_t b) {
    uint64_t d; asm("mul.rn.f32x2 %0, %1, %2;" : "=l"(d) : "l"(a), "l"(b));
    return d;
}

// ---------------------------------------------------------------------------
// fp32 -> (bf16 hi, bf16 lo) split
// ---------------------------------------------------------------------------
__global__ void __launch_bounds__(256)
split_kernel(const float4* __restrict__ src, __nv_bfloat162* __restrict__ hi,
             __nv_bfloat162* __restrict__ lo, int n4)
{
    int i = blockIdx.x * blockDim.x + threadIdx.x;
    if (i >= n4) return;
    float4 v = src[i];
    __nv_bfloat16 hx = __float2bfloat16(v.x);
    __nv_bfloat16 hy = __float2bfloat16(v.y);
    __nv_bfloat16 hz = __float2bfloat16(v.z);
    __nv_bfloat16 hw = __float2bfloat16(v.w);
    __nv_bfloat16 lx = __float2bfloat16(v.x - __bfloat162float(hx));
    __nv_bfloat16 ly = __float2bfloat16(v.y - __bfloat162float(hy));
    __nv_bfloat16 lz = __float2bfloat16(v.z - __bfloat162float(hz));
    __nv_bfloat16 lw = __float2bfloat16(v.w - __bfloat162float(hw));
    hi[2 * i + 0] = __nv_bfloat162(hx, hy);
    hi[2 * i + 1] = __nv_bfloat162(hz, hw);
    lo[2 * i + 0] = __nv_bfloat162(lx, ly);
    lo[2 * i + 1] = __nv_bfloat162(lz, lw);
}

// ---------------------------------------------------------------------------
// Split-bf16 HMMA GEMM (NT): C[m,n] = sum_k A[m,k]*B[n,k] + bias[n]
// 128x128 CTA tile, BK=32, 8 warps (2M x 4N, 64x32 warp tile), cp.async
// double buffer. Smem rows padded to 40 bf16 (80B) for conflict-free ldmatrix.
// ---------------------------------------------------------------------------
#define ROWB   80                       // bytes per smem row
#define ARR_B  (128 * ROWB)             // 10240 B per array
#define STAGE_B (4 * ARR_B)             // 40960 B per stage
#define GEMM_SMEM (2 * STAGE_B)         // 81920 B

__global__ void __launch_bounds__(256, 1)
gemm_hmma(const __nv_bfloat16* __restrict__ Ahi, const __nv_bfloat16* __restrict__ Alo,
          const __nv_bfloat16* __restrict__ Bhi, const __nv_bfloat16* __restrict__ Blo,
          const float* __restrict__ bias, float* __restrict__ C,
          int M, int N, int K)
{
    extern __shared__ char sm[];
    const int tid  = threadIdx.x;
    const int wid  = tid >> 5;
    const int lane = tid & 31;
    const int wm   = wid & 1;           // 0..1  (M)
    const int wn   = wid >> 1;          // 0..3  (N)
    const int row0 = blockIdx.y * 128;
    const int col0 = blockIdx.x * 128;

    const uint32_t smb = smem_u32(sm);

    // gmem->smem copy mapping: per array, 512 x 16B; thread does 2.
    const int lr = tid >> 2;            // 0..63
    const int lc = tid & 3;             // 16B column chunk

    auto ld_chunk = [&](int i, int stage) {
        const int k0 = i * 32;
        uint32_t sb = smb + stage * STAGE_B;
        #pragma unroll
        for (int rep = 0; rep < 2; rep++) {
            int rr = lr + rep * 64;
            size_t goA = (size_t)(row0 + rr) * K + k0 + lc * 8;
            size_t goB = (size_t)(col0 + rr) * K + k0 + lc * 8;
            uint32_t so = rr * ROWB + lc * 16;
            CP_ASYNC16(sb +             so, Ahi + goA);
            CP_ASYNC16(sb + ARR_B +     so, Alo + goA);
            CP_ASYNC16(sb + 2 * ARR_B + so, Bhi + goB);
            CP_ASYNC16(sb + 3 * ARR_B + so, Blo + goB);
        }
    };

    float acc[4][4][4];
    #pragma unroll
    for (int i = 0; i < 4; i++)
        #pragma unroll
        for (int j = 0; j < 4; j++)
            #pragma unroll
            for (int v = 0; v < 4; v++) acc[i][j][v] = 0.f;

    // ldmatrix lane addressing
    const int arow = (lane & 7) + ((lane >> 3) & 1) * 8;   // 0..15
    const int akb  = (lane >> 4) * 16;                     // 0 / 16
    const uint32_t aoff = (uint32_t)((wm * 64 + arow) * ROWB + akb);
    const uint32_t boff = (uint32_t)((wn * 32 + (lane & 7)) * ROWB + ((lane >> 3) & 1) * 16);

    const int NC = K / 32;
    ld_chunk(0, 0);
    CP_COMMIT();
    CP_WAIT0();
    __syncthreads();

    for (int i = 0; i < NC; i++) {
        const int st = i & 1;
        if (i + 1 < NC) { ld_chunk(i + 1, st ^ 1); CP_COMMIT(); }

        const uint32_t sA  = smb + st * STAGE_B;
        const uint32_t sAl = sA + ARR_B;
        const uint32_t sB  = sA + 2 * ARR_B;
        const uint32_t sBl = sA + 3 * ARR_B;

        #pragma unroll
        for (int ks = 0; ks < 2; ks++) {
            uint32_t ah[4][4], al[4][4], bh[4][2], bl[4][2];
            #pragma unroll
            for (int fi = 0; fi < 4; fi++) {
                ldsm4(ah[fi], sA  + aoff + fi * 16 * ROWB + ks * 32);
                ldsm4(al[fi], sAl + aoff + fi * 16 * ROWB + ks * 32);
            }
            #pragma unroll
            for (int fj = 0; fj < 4; fj++) {
                ldsm2(bh[fj], sB  + boff + fj * 8 * ROWB + ks * 32);
                ldsm2(bl[fj], sBl + boff + fj * 8 * ROWB + ks * 32);
            }
            #pragma unroll
            for (int fi = 0; fi < 4; fi++)
                #pragma unroll
                for (int fj = 0; fj < 4; fj++) {
                    mma16816(acc[fi][fj], ah[fi], bh[fj]);
                    mma16816(acc[fi][fj], ah[fi], bl[fj]);
                    mma16816(acc[fi][fj], al[fi], bh[fj]);
                }
        }
        if (i + 1 < NC) CP_WAIT0();
        __syncthreads();
    }

    // Epilogue: d-frag lane layout -> direct fp32 stores with bias.
    #pragma unroll
    for (int fi = 0; fi < 4; fi++) {
        const int r = row0 + wm * 64 + fi * 16 + (lane >> 2);
        #pragma unroll
        for (int fj = 0; fj < 4; fj++) {
            const int cc = col0 + wn * 32 + fj * 8 + (lane & 3) * 2;
            float2 bb = *(const float2*)&bias[cc];
            float2 v0 = make_float2(acc[fi][fj][0] + bb.x, acc[fi][fj][1] + bb.y);
            float2 v1 = make_float2(acc[fi][fj][2] + bb.x, acc[fi][fj][3] + bb.y);
            *(float2*)&C[(size_t)r * N + cc]       = v0;
            *(float2*)&C[(size_t)(r + 8) * N + cc] = v1;
        }
    }
}

// ---------------------------------------------------------------------------
// Flash attention, packed f32x2 math. One thread per query row.
// Writes bf16 hi/lo split for GEMM2.
// ---------------------------------------------------------------------------
__global__ void __launch_bounds__(128, 1)
attn_kernel(const float* __restrict__ qkv,
            __nv_bfloat16* __restrict__ out_hi, __nv_bfloat16* __restrict__ out_lo)
{
    __shared__ float Ks[32][HEAD_D];
    __shared__ float Vs[32][HEAD_D];

    const int tid = threadIdx.x;
    const int h   = blockIdx.y & (NHEAD - 1);
    const int b   = blockIdx.y >> 4;
    const int qrow = blockIdx.x * 128 + tid;
    const int hofs = h * 3 * HEAD_D;

    uint64_t q2[HEAD_D / 2];
    {
        const float4* qp = (const float4*)(qkv + ((size_t)(b * S_LEN + qrow)) * TDQ + hofs);
        #pragma unroll
        for (int j = 0; j < 16; j++) {
            float4 t = qp[j];
            q2[2 * j + 0] = pack2(t.x * 0.125f, t.y * 0.125f);
            q2[2 * j + 1] = pack2(t.z * 0.125f, t.w * 0.125f);
        }
    }

    uint64_t o2[HEAD_D / 2];
    #pragma unroll
    for (int j = 0; j < HEAD_D / 2; j++) o2[j] = 0ull;
    float m = -1e30f, l = 0.f;

    for (int kt = 0; kt < S_LEN; kt += 32) {
        #pragma unroll
        for (int it = 0; it < 4; it++) {
            int fid = tid + it * 128;
            int r = fid >> 4;
            int c = (fid & 15) * 4;
            const float* src = qkv + ((size_t)(b * S_LEN + kt + r)) * TDQ + hofs;
            *(float4*)&Ks[r][c] = *(const float4*)(src + HEAD_D + c);
            *(float4*)&Vs[r][c] = *(const float4*)(src + 2 * HEAD_D + c);
        }
        __syncthreads();

        float p[32];
        float mt = -1e30f;
        #pragma unroll
        for (int kk = 0; kk < 32; kk++) {
            const uint64_t* krow = (const uint64_t*)&Ks[kk][0];
            uint64_t a0 = 0ull, a1 = 0ull;
            #pragma unroll
            for (int j = 0; j < HEAD_D / 4; j++) {
                a0 = fma2(q2[2 * j + 0], krow[2 * j + 0], a0);
                a1 = fma2(q2[2 * j + 1], krow[2 * j + 1], a1);
            }
            float x0, x1, y0, y1;
            unpack2(a0, x0, x1);
            unpack2(a1, y0, y1);
            float s = (x0 + x1) + (y0 + y1);
            p[kk] = s;
            mt = fmaxf(mt, s);
        }

        const float mnew  = fmaxf(m, mt);
        const float alpha = __expf(m - mnew);
        float ls = 0.f;
        #pragma unroll
        for (int kk = 0; kk < 32; kk++) {
            p[kk] = __expf(p[kk] - mnew);
            ls += p[kk];
        }
        l = l * alpha + ls;
        m = mnew;

        const uint64_t al2 = pack2(alpha, alpha);
        #pragma unroll
        for (int j = 0; j < HEAD_D / 2; j++) o2[j] = mul2(o2[j], al2);

        #pragma unroll
        for (int kk = 0; kk < 32; kk++) {
            const uint64_t pk2 = pack2(p[kk], p[kk]);
            const uint64_t* vrow = (const uint64_t*)&Vs[kk][0];
            #pragma unroll
            for (int j = 0; j < HEAD_D / 2; j++)
                o2[j] = fma2(pk2, vrow[j], o2[j]);
        }
        __syncthreads();
    }

    const float inv = 1.f / l;
    const size_t base = ((size_t)(b * S_LEN + qrow)) * D_MODEL + h * HEAD_D;
    #pragma unroll
    for (int j = 0; j < HEAD_D / 2; j++) {
        float v0, v1;
        unpack2(o2[j], v0, v1);
        v0 *= inv; v1 *= inv;
        __nv_bfloat16 h0 = __float2bfloat16(v0);
        __nv_bfloat16 h1 = __float2bfloat16(v1);
        __nv_bfloat16 l0 = __float2bfloat16(v0 - __bfloat162float(h0));
        __nv_bfloat16 l1 = __float2bfloat16(v1 - __bfloat162float(h1));
        *(__nv_bfloat162*)(out_hi + base + 2 * j) = __nv_bfloat162(h0, h1);
        *(__nv_bfloat162*)(out_lo + base + 2 * j) = __nv_bfloat162(l0, l1);
    }
}

// ---------------------------------------------------------------------------
extern "C" void kernel_launch(void* const* d_in, const int* in_sizes, int n_in,
                              void* d_out, int out_size)
{
    const float* x     = (const float*)d_in[0];
    const float* w_qkv = (const float*)d_in[1];
    const float* b_qkv = (const float*)d_in[2];
    const float* w_o   = (const float*)d_in[3];
    const float* b_o   = (const float*)d_in[4];
    float* out = (float*)d_out;

    float* qkv;
    __nv_bfloat16 *xh, *xl, *wqh, *wql, *woh, *wol, *ath, *atl;
    cudaGetSymbolAddress((void**)&qkv, g_qkv);
    cudaGetSymbolAddress((void**)&xh,  g_x_hi);  cudaGetSymbolAddress((void**)&xl,  g_x_lo);
    cudaGetSymbolAddress((void**)&wqh, g_wq_hi); cudaGetSymbolAddress((void**)&wql, g_wq_lo);
    cudaGetSymbolAddress((void**)&woh, g_wo_hi); cudaGetSymbolAddress((void**)&wol, g_wo_lo);
    cudaGetSymbolAddress((void**)&ath, g_at_hi); cudaGetSymbolAddress((void**)&atl, g_at_lo);

    cudaFuncSetAttribute(gemm_hmma, cudaFuncAttributeMaxDynamicSharedMemorySize, GEMM_SMEM);

    // splits
    {
        int n4 = M_ROWS * KDIM / 4;
        split_kernel<<<(n4 + 255) / 256, 256>>>((const float4*)x,
            (__nv_bfloat162*)xh, (__nv_bfloat162*)xl, n4);
    }
    {
        int n4 = TDQ * KDIM / 4;
        split_kernel<<<(n4 + 255) / 256, 256>>>((const float4*)w_qkv,
            (__nv_bfloat162*)wqh, (__nv_bfloat162*)wql, n4);
    }
    {
        int n4 = D_MODEL * KDIM / 4;
        split_kernel<<<(n4 + 255) / 256, 256>>>((const float4*)w_o,
            (__nv_bfloat162*)wol ? (__nv_bfloat162*)woh : nullptr,  // (kept simple below)
            (__nv_bfloat162*)wol, n4);
    }
    // NOTE: fix-up — the ternary above must not perturb; re-issue properly:
    {
        int n4 = D_MODEL * KDIM / 4;
        split_kernel<<<(n4 + 255) / 256, 256>>>((const float4*)w_o,
            (__nv_bfloat162*)woh, (__nv_bfloat162*)wol, n4);
    }

    // 1) QKV projection: [8192,3072]
    {
        dim3 grid(TDQ / 128, M_ROWS / 128);
        gemm_hmma<<<grid, 256, GEMM_SMEM>>>(xh, xl, wqh, wql, b_qkv, qkv,
                                            M_ROWS, TDQ, KDIM);
    }
    // 2) attention -> bf16 hi/lo
    {
        dim3 grid(S_LEN / 128, BATCH * NHEAD);
        attn_kernel<<<grid, 128>>>(qkv, ath, atl);
    }
    // 3) output projection: [8192,1024]
    {
        dim3 grid(D_MODEL / 128, M_ROWS / 128);
        gemm_hmma<<<grid, 256, GEMM_SMEM>>>(ath, atl, woh, wol, b_o, out,
                                            M_ROWS, D_MODEL, KDIM);
    }
}

// round 4
// speedup vs baseline: 2.7542x; 1.7106x over previous
#include <cuda_runtime.h>
#include <cuda_bf16.h>
#include <cstdint>
#include <cstddef>

// Problem constants
#define BATCH   4
#define S_LEN   2048
#define D_MODEL 1024
#define NHEAD   16
#define HEAD_D  64
#define TDQ     (3 * D_MODEL)          // 3072
#define M_ROWS  (BATCH * S_LEN)        // 8192
#define KDIM    D_MODEL                // 1024
#define BH      (BATCH * NHEAD)        // 64

// ---------------------------------------------------------------------------
// Scratch (__device__ globals; allocation-free rule)
// ---------------------------------------------------------------------------
__device__ __align__(128) float         g_qkv   [(size_t)M_ROWS * TDQ];
__device__ __align__(128) __nv_bfloat16 g_x_hi  [(size_t)M_ROWS * KDIM];
__device__ __align__(128) __nv_bfloat16 g_x_lo  [(size_t)M_ROWS * KDIM];
__device__ __align__(128) __nv_bfloat16 g_wq_hi [(size_t)TDQ    * KDIM];
__device__ __align__(128) __nv_bfloat16 g_wq_lo [(size_t)TDQ    * KDIM];
__device__ __align__(128) __nv_bfloat16 g_wo_hi [(size_t)D_MODEL* KDIM];
__device__ __align__(128) __nv_bfloat16 g_wo_lo [(size_t)D_MODEL* KDIM];
__device__ __align__(128) __nv_bfloat16 g_at_hi [(size_t)M_ROWS * D_MODEL];
__device__ __align__(128) __nv_bfloat16 g_at_lo [(size_t)M_ROWS * D_MODEL];
// attention-ready planes
__device__ __align__(128) __nv_bfloat16 g_q_hi  [(size_t)BH * S_LEN * HEAD_D];
__device__ __align__(128) __nv_bfloat16 g_q_lo  [(size_t)BH * S_LEN * HEAD_D];
__device__ __align__(128) __nv_bfloat16 g_k_hi  [(size_t)BH * S_LEN * HEAD_D];
__device__ __align__(128) __nv_bfloat16 g_k_lo  [(size_t)BH * S_LEN * HEAD_D];
__device__ __align__(128) __nv_bfloat16 g_vt_hi [(size_t)BH * HEAD_D * S_LEN];
__device__ __align__(128) __nv_bfloat16 g_vt_lo [(size_t)BH * HEAD_D * S_LEN];

// ---------------------------------------------------------------------------
// Helpers
// ---------------------------------------------------------------------------
__device__ __forceinline__ uint32_t smem_u32(const void* p) {
    uint32_t a;
    asm("{ .reg .u64 t; cvta.to.shared.u64 t, %1; cvt.u32.u64 %0, t; }"
        : "=r"(a) : "l"(p));
    return a;
}

#define CP_ASYNC16(saddr, gptr) \
    asm volatile("cp.async.cg.shared.global [%0], [%1], 16;" :: "r"(saddr), "l"(gptr))
#define CP_COMMIT() asm volatile("cp.async.commit_group;" ::: "memory")
#define CP_WAIT0()  asm volatile("cp.async.wait_group 0;" ::: "memory")

__device__ __forceinline__ void ldsm4(uint32_t* r, uint32_t addr) {
    asm volatile("ldmatrix.sync.aligned.m8n8.x4.shared.b16 {%0,%1,%2,%3}, [%4];"
                 : "=r"(r[0]), "=r"(r[1]), "=r"(r[2]), "=r"(r[3]) : "r"(addr));
}
__device__ __forceinline__ void ldsm2(uint32_t* r, uint32_t addr) {
    asm volatile("ldmatrix.sync.aligned.m8n8.x2.shared.b16 {%0,%1}, [%2];"
                 : "=r"(r[0]), "=r"(r[1]) : "r"(addr));
}
__device__ __forceinline__ void mma16816(float* d, const uint32_t* a, const uint32_t* b) {
    asm volatile(
        "mma.sync.aligned.m16n8k16.row.col.f32.bf16.bf16.f32 "
        "{%0,%1,%2,%3}, {%4,%5,%6,%7}, {%8,%9}, {%0,%1,%2,%3};"
        : "+f"(d[0]), "+f"(d[1]), "+f"(d[2]), "+f"(d[3])
        : "r"(a[0]), "r"(a[1]), "r"(a[2]), "r"(a[3]), "r"(b[0]), "r"(b[1]));
}

__device__ __forceinline__ void split1(float x, __nv_bfloat16& h, __nv_bfloat16& l) {
    h = __float2bfloat16(x);
    l = __float2bfloat16(x - __bfloat162float(h));
}
__device__ __forceinline__ void split2_pack(float x, float y, uint32_t& hi, uint32_t& lo) {
    __nv_bfloat16 hx, lx, hy, ly;
    split1(x, hx, lx); split1(y, hy, ly);
    __nv_bfloat162 th(hx, hy), tl(lx, ly);
    hi = *(uint32_t*)&th; lo = *(uint32_t*)&tl;
}

// ---------------------------------------------------------------------------
// fp32 -> (bf16 hi, bf16 lo) split
// ---------------------------------------------------------------------------
__global__ void __launch_bounds__(256)
split_kernel(const float4* __restrict__ src, __nv_bfloat162* __restrict__ hi,
             __nv_bfloat162* __restrict__ lo, int n4)
{
    int i = blockIdx.x * blockDim.x + threadIdx.x;
    if (i >= n4) return;
    float4 v = src[i];
    __nv_bfloat16 hx, lx, hy, ly, hz, lz, hw, lw;
    split1(v.x, hx, lx); split1(v.y, hy, ly);
    split1(v.z, hz, lz); split1(v.w, hw, lw);
    hi[2 * i + 0] = __nv_bfloat162(hx, hy);
    hi[2 * i + 1] = __nv_bfloat162(hz, hw);
    lo[2 * i + 0] = __nv_bfloat162(lx, ly);
    lo[2 * i + 1] = __nv_bfloat162(lz, lw);
}

// ---------------------------------------------------------------------------
// Split-bf16 HMMA GEMM (NT) — unchanged from R3 (verified).
// ---------------------------------------------------------------------------
#define ROWB   80
#define ARR_B  (128 * ROWB)
#define STAGE_B (4 * ARR_B)
#define GEMM_SMEM (2 * STAGE_B)

__global__ void __launch_bounds__(256, 1)
gemm_hmma(const __nv_bfloat16* __restrict__ Ahi, const __nv_bfloat16* __restrict__ Alo,
          const __nv_bfloat16* __restrict__ Bhi, const __nv_bfloat16* __restrict__ Blo,
          const float* __restrict__ bias, float* __restrict__ C,
          int M, int N, int K)
{
    extern __shared__ char sm[];
    const int tid  = threadIdx.x;
    const int wid  = tid >> 5;
    const int lane = tid & 31;
    const int wm   = wid & 1;
    const int wn   = wid >> 1;
    const int row0 = blockIdx.y * 128;
    const int col0 = blockIdx.x * 128;

    const uint32_t smb = smem_u32(sm);
    const int lr = tid >> 2;
    const int lc = tid & 3;

    auto ld_chunk = [&](int i, int stage) {
        const int k0 = i * 32;
        uint32_t sb = smb + stage * STAGE_B;
        #pragma unroll
        for (int rep = 0; rep < 2; rep++) {
            int rr = lr + rep * 64;
            size_t goA = (size_t)(row0 + rr) * K + k0 + lc * 8;
            size_t goB = (size_t)(col0 + rr) * K + k0 + lc * 8;
            uint32_t so = rr * ROWB + lc * 16;
            CP_ASYNC16(sb +             so, Ahi + goA);
            CP_ASYNC16(sb + ARR_B +     so, Alo + goA);
            CP_ASYNC16(sb + 2 * ARR_B + so, Bhi + goB);
            CP_ASYNC16(sb + 3 * ARR_B + so, Blo + goB);
        }
    };

    float acc[4][4][4];
    #pragma unroll
    for (int i = 0; i < 4; i++)
        #pragma unroll
        for (int j = 0; j < 4; j++)
            #pragma unroll
            for (int v = 0; v < 4; v++) acc[i][j][v] = 0.f;

    const int arow = (lane & 7) + ((lane >> 3) & 1) * 8;
    const int akb  = (lane >> 4) * 16;
    const uint32_t aoff = (uint32_t)((wm * 64 + arow) * ROWB + akb);
    const uint32_t boff = (uint32_t)((wn * 32 + (lane & 7)) * ROWB + ((lane >> 3) & 1) * 16);

    const int NC = K / 32;
    ld_chunk(0, 0);
    CP_COMMIT();
    CP_WAIT0();
    __syncthreads();

    for (int i = 0; i < NC; i++) {
        const int st = i & 1;
        if (i + 1 < NC) { ld_chunk(i + 1, st ^ 1); CP_COMMIT(); }

        const uint32_t sA  = smb + st * STAGE_B;
        const uint32_t sAl = sA + ARR_B;
        const uint32_t sB  = sA + 2 * ARR_B;
        const uint32_t sBl = sA + 3 * ARR_B;

        #pragma unroll
        for (int ks = 0; ks < 2; ks++) {
            uint32_t ah[4][4], al[4][4], bh[4][2], bl[4][2];
            #pragma unroll
            for (int fi = 0; fi < 4; fi++) {
                ldsm4(ah[fi], sA  + aoff + fi * 16 * ROWB + ks * 32);
                ldsm4(al[fi], sAl + aoff + fi * 16 * ROWB + ks * 32);
            }
            #pragma unroll
            for (int fj = 0; fj < 4; fj++) {
                ldsm2(bh[fj], sB  + boff + fj * 8 * ROWB + ks * 32);
                ldsm2(bl[fj], sBl + boff + fj * 8 * ROWB + ks * 32);
            }
            #pragma unroll
            for (int fi = 0; fi < 4; fi++)
                #pragma unroll
                for (int fj = 0; fj < 4; fj++) {
                    mma16816(acc[fi][fj], ah[fi], bh[fj]);
                    mma16816(acc[fi][fj], ah[fi], bl[fj]);
                    mma16816(acc[fi][fj], al[fi], bh[fj]);
                }
        }
        if (i + 1 < NC) CP_WAIT0();
        __syncthreads();
    }

    #pragma unroll
    for (int fi = 0; fi < 4; fi++) {
        const int r = row0 + wm * 64 + fi * 16 + (lane >> 2);
        #pragma unroll
        for (int fj = 0; fj < 4; fj++) {
            const int cc = col0 + wn * 32 + fj * 8 + (lane & 3) * 2;
            float2 bb = *(const float2*)&bias[cc];
            float2 v0 = make_float2(acc[fi][fj][0] + bb.x, acc[fi][fj][1] + bb.y);
            float2 v1 = make_float2(acc[fi][fj][2] + bb.x, acc[fi][fj][3] + bb.y);
            *(float2*)&C[(size_t)r * N + cc]       = v0;
            *(float2*)&C[(size_t)(r + 8) * N + cc] = v1;
        }
    }
}

// ---------------------------------------------------------------------------
// Prep: qkv fp32 [token][3072] -> per-(b,h) planes:
//   Q hi/lo [bh][s][64] (scaled by 1/8), K hi/lo [bh][s][64],
//   V^T hi/lo [bh][d][s].
// One thread per (bh, token).
// ---------------------------------------------------------------------------
__global__ void __launch_bounds__(256)
prep_qkv(const float* __restrict__ qkv,
         __nv_bfloat16* __restrict__ qh, __nv_bfloat16* __restrict__ ql,
         __nv_bfloat16* __restrict__ kh, __nv_bfloat16* __restrict__ kl,
         __nv_bfloat16* __restrict__ vth, __nv_bfloat16* __restrict__ vtl)
{
    const int s  = blockIdx.x * 256 + threadIdx.x;
    const int bh = blockIdx.y;
    const int b  = bh >> 4;
    const int h  = bh & 15;
    const float* src = qkv + ((size_t)(b * S_LEN + s)) * TDQ + h * 3 * HEAD_D;

    __nv_bfloat16* qhp = qh + ((size_t)bh * S_LEN + s) * HEAD_D;
    __nv_bfloat16* qlp = ql + ((size_t)bh * S_LEN + s) * HEAD_D;
    __nv_bfloat16* khp = kh + ((size_t)bh * S_LEN + s) * HEAD_D;
    __nv_bfloat16* klp = kl + ((size_t)bh * S_LEN + s) * HEAD_D;

    #pragma unroll
    for (int j = 0; j < 16; j++) {
        float4 qv = *(const float4*)(src + 4 * j);
        float4 kv = *(const float4*)(src + HEAD_D + 4 * j);
        __nv_bfloat16 hh, ll;
        split1(qv.x * 0.125f, hh, ll); qhp[4*j+0] = hh; qlp[4*j+0] = ll;
        split1(qv.y * 0.125f, hh, ll); qhp[4*j+1] = hh; qlp[4*j+1] = ll;
        split1(qv.z * 0.125f, hh, ll); qhp[4*j+2] = hh; qlp[4*j+2] = ll;
        split1(qv.w * 0.125f, hh, ll); qhp[4*j+3] = hh; qlp[4*j+3] = ll;
        split1(kv.x, hh, ll); khp[4*j+0] = hh; klp[4*j+0] = ll;
        split1(kv.y, hh, ll); khp[4*j+1] = hh; klp[4*j+1] = ll;
        split1(kv.z, hh, ll); khp[4*j+2] = hh; klp[4*j+2] = ll;
        split1(kv.w, hh, ll); khp[4*j+3] = hh; klp[4*j+3] = ll;
    }
    // V transpose: [bh][d][s]
    #pragma unroll
    for (int j = 0; j < 16; j++) {
        float4 vv = *(const float4*)(src + 2 * HEAD_D + 4 * j);
        #pragma unroll
        for (int e = 0; e < 4; e++) {
            float val = (e == 0) ? vv.x : (e == 1) ? vv.y : (e == 2) ? vv.z : vv.w;
            int d = 4 * j + e;
            __nv_bfloat16 hh, ll;
            split1(val, hh, ll);
            vth[((size_t)bh * HEAD_D + d) * S_LEN + s] = hh;
            vtl[((size_t)bh * HEAD_D + d) * S_LEN + s] = ll;
        }
    }
}

// ---------------------------------------------------------------------------
// Flash attention on HMMA. CTA: 128 q rows, 8 warps x 16 rows, 64-key tiles.
// ---------------------------------------------------------------------------
#define AROW     144                   // smem row stride (128B data + 16 pad)
#define Q_ARR    (128 * AROW)          // 18432
#define T_ARR    (64 * AROW)           // 9216
#define T_STAGE  (4 * T_ARR)           // 36864 (Kh,Kl,Vh,Vl)
#define ATTN_SMEM (2 * Q_ARR + 2 * T_STAGE)   // 110592

__global__ void __launch_bounds__(256, 1)
attn_mma(const __nv_bfloat16* __restrict__ qh, const __nv_bfloat16* __restrict__ ql,
         const __nv_bfloat16* __restrict__ kh, const __nv_bfloat16* __restrict__ kl,
         const __nv_bfloat16* __restrict__ vth, const __nv_bfloat16* __restrict__ vtl,
         __nv_bfloat16* __restrict__ outh, __nv_bfloat16* __restrict__ outl)
{
    extern __shared__ char sm[];
    const uint32_t smb = smem_u32(sm);
    const int tid  = threadIdx.x;
    const int wid  = tid >> 5;
    const int lane = tid & 31;
    const int bh = blockIdx.y;
    const int qb = blockIdx.x;

    const __nv_bfloat16* Qh = qh + ((size_t)bh * S_LEN + qb * 128) * HEAD_D;
    const __nv_bfloat16* Ql = ql + ((size_t)bh * S_LEN + qb * 128) * HEAD_D;
    const __nv_bfloat16* Kh = kh + (size_t)bh * S_LEN * HEAD_D;
    const __nv_bfloat16* Kl = kl + (size_t)bh * S_LEN * HEAD_D;
    const __nv_bfloat16* Vh = vth + (size_t)bh * HEAD_D * S_LEN;
    const __nv_bfloat16* Vl = vtl + (size_t)bh * HEAD_D * S_LEN;

    auto ld_tile = [&](int kt, int st) {
        const int k0 = kt * 64;
        const uint32_t sb = smb + 2 * Q_ARR + st * T_STAGE;
        #pragma unroll
        for (int rep = 0; rep < 2; rep++) {
            int idx = tid + rep * 256;        // 0..511
            int row = idx >> 3;               // 0..63
            int ch  = idx & 7;
            uint32_t so = row * AROW + ch * 16;
            const __nv_bfloat16* gk = Kh + (size_t)(k0 + row) * HEAD_D + ch * 8;
            const __nv_bfloat16* gkl= Kl + (size_t)(k0 + row) * HEAD_D + ch * 8;
            const __nv_bfloat16* gv = Vh + (size_t)row * S_LEN + k0 + ch * 8;
            const __nv_bfloat16* gvl= Vl + (size_t)row * S_LEN + k0 + ch * 8;
            CP_ASYNC16(sb +             so, gk);
            CP_ASYNC16(sb + T_ARR +     so, gkl);
            CP_ASYNC16(sb + 2 * T_ARR + so, gv);
            CP_ASYNC16(sb + 3 * T_ARR + so, gvl);
        }
    };

    // Q tile -> smem (once)
    #pragma unroll
    for (int rep = 0; rep < 4; rep++) {
        int idx = tid + rep * 256;            // 0..1023
        int row = idx >> 3;                   // 0..127
        int ch  = idx & 7;
        uint32_t so = row * AROW + ch * 16;
        CP_ASYNC16(smb +         so, Qh + (size_t)row * HEAD_D + ch * 8);
        CP_ASYNC16(smb + Q_ARR + so, Ql + (size_t)row * HEAD_D + ch * 8);
    }
    ld_tile(0, 0);
    CP_COMMIT();
    CP_WAIT0();
    __syncthreads();

    // Q fragments (register resident)
    const int arow = (lane & 7) + ((lane >> 3) & 1) * 8;
    const int akb  = (lane >> 4) * 16;
    const uint32_t qbase = smb + (uint32_t)((wid * 16 + arow) * AROW + akb);
    uint32_t qfh[4][4], qfl[4][4];
    #pragma unroll
    for (int kk = 0; kk < 4; kk++) {
        ldsm4(qfh[kk], qbase + kk * 32);
        ldsm4(qfl[kk], qbase + Q_ARR + kk * 32);
    }

    float o[8][4];
    #pragma unroll
    for (int nf = 0; nf < 8; nf++)
        #pragma unroll
        for (int v = 0; v < 4; v++) o[nf][v] = 0.f;
    float m0 = -1e30f, m1 = -1e30f, l0 = 0.f, l1 = 0.f;

    const uint32_t bo = (uint32_t)((lane & 7) * AROW + ((lane >> 3) & 1) * 16);
    const int NT = S_LEN / 64;

    for (int kt = 0; kt < NT; kt++) {
        const int st = kt & 1;
        if (kt + 1 < NT) { ld_tile(kt + 1, st ^ 1); CP_COMMIT(); }

        const uint32_t base_k = smb + 2 * Q_ARR + st * T_STAGE;
        const uint32_t base_v = base_k + 2 * T_ARR;

        // ---- logits S = Q K^T (3 passes) ----
        float s_[8][4];
        #pragma unroll
        for (int nf = 0; nf < 8; nf++)
            #pragma unroll
            for (int v = 0; v < 4; v++) s_[nf][v] = 0.f;

        #pragma unroll
        for (int nf = 0; nf < 8; nf++) {
            #pragma unroll
            for (int kk = 0; kk < 4; kk++) {
                uint32_t addr = base_k + bo + nf * 8 * AROW + kk * 32;
                uint32_t kbh[2], kbl[2];
                ldsm2(kbh, addr);
                ldsm2(kbl, addr + T_ARR);
                mma16816(s_[nf], qfh[kk], kbh);
                mma16816(s_[nf], qfh[kk], kbl);
                mma16816(s_[nf], qfl[kk], kbh);
            }
        }

        // ---- online softmax ----
        float tm0 = -1e30f, tm1 = -1e30f;
        #pragma unroll
        for (int nf = 0; nf < 8; nf++) {
            tm0 = fmaxf(tm0, fmaxf(s_[nf][0], s_[nf][1]));
            tm1 = fmaxf(tm1, fmaxf(s_[nf][2], s_[nf][3]));
        }
        tm0 = fmaxf(tm0, __shfl_xor_sync(0xffffffffu, tm0, 1));
        tm0 = fmaxf(tm0, __shfl_xor_sync(0xffffffffu, tm0, 2));
        tm1 = fmaxf(tm1, __shfl_xor_sync(0xffffffffu, tm1, 1));
        tm1 = fmaxf(tm1, __shfl_xor_sync(0xffffffffu, tm1, 2));

        const float mn0 = fmaxf(m0, tm0);
        const float mn1 = fmaxf(m1, tm1);
        const float a0 = __expf(m0 - mn0);
        const float a1 = __expf(m1 - mn1);
        m0 = mn0; m1 = mn1;

        float sum0 = 0.f, sum1 = 0.f;
        #pragma unroll
        for (int nf = 0; nf < 8; nf++) {
            s_[nf][0] = __expf(s_[nf][0] - m0);
            s_[nf][1] = __expf(s_[nf][1] - m0);
            s_[nf][2] = __expf(s_[nf][2] - m1);
            s_[nf][3] = __expf(s_[nf][3] - m1);
            sum0 += s_[nf][0] + s_[nf][1];
            sum1 += s_[nf][2] + s_[nf][3];
        }
        sum0 += __shfl_xor_sync(0xffffffffu, sum0, 1);
        sum0 += __shfl_xor_sync(0xffffffffu, sum0, 2);
        sum1 += __shfl_xor_sync(0xffffffffu, sum1, 1);
        sum1 += __shfl_xor_sync(0xffffffffu, sum1, 2);
        l0 = l0 * a0 + sum0;
        l1 = l1 * a1 + sum1;

        #pragma unroll
        for (int nf = 0; nf < 8; nf++) {
            o[nf][0] *= a0; o[nf][1] *= a0;
            o[nf][2] *= a1; o[nf][3] *= a1;
        }

        // ---- P -> A fragments (hi/lo) ----
        uint32_t pah[4][4], pal[4][4];
        #pragma unroll
        for (int kk = 0; kk < 4; kk++) {
            const int n0 = 2 * kk, n1 = 2 * kk + 1;
            split2_pack(s_[n0][0], s_[n0][1], pah[kk][0], pal[kk][0]);
            split2_pack(s_[n0][2], s_[n0][3], pah[kk][1], pal[kk][1]);
            split2_pack(s_[n1][0], s_[n1][1], pah[kk][2], pal[kk][2]);
            split2_pack(s_[n1][2], s_[n1][3], pah[kk][3], pal[kk][3]);
        }

        // ---- O += P V (3 passes), B = V^T tile [dim][key] ----
        #pragma unroll
        for (int nf = 0; nf < 8; nf++) {
            #pragma unroll
            for (int kk = 0; kk < 4; kk++) {
                uint32_t addr = base_v + bo + nf * 8 * AROW + kk * 32;
                uint32_t vbh[2], vbl[2];
                ldsm2(vbh, addr);
                ldsm2(vbl, addr + T_ARR);
                mma16816(o[nf], pah[kk], vbh);
                mma16816(o[nf], pah[kk], vbl);
                mma16816(o[nf], pal[kk], vbh);
            }
        }

        if (kt + 1 < NT) CP_WAIT0();
        __syncthreads();
    }

    // ---- epilogue: o/l -> bf16 hi/lo into [token][1024] ----
    const float inv0 = 1.f / l0;
    const float inv1 = 1.f / l1;
    const int b = bh >> 4;
    const int h = bh & 15;
    const int r0 = qb * 128 + wid * 16 + (lane >> 2);
    const size_t tok0 = (size_t)(b * S_LEN + r0) * D_MODEL;
    const size_t tok1 = (size_t)(b * S_LEN + r0 + 8) * D_MODEL;
    #pragma unroll
    for (int nf = 0; nf < 8; nf++) {
        const int col = h * HEAD_D + nf * 8 + (lane & 3) * 2;
        uint32_t hi, lo;
        split2_pack(o[nf][0] * inv0, o[nf][1] * inv0, hi, lo);
        *(uint32_t*)(outh + tok0 + col) = hi;
        *(uint32_t*)(outl + tok0 + col) = lo;
        split2_pack(o[nf][2] * inv1, o[nf][3] * inv1, hi, lo);
        *(uint32_t*)(outh + tok1 + col) = hi;
        *(uint32_t*)(outl + tok1 + col) = lo;
    }
}

// ---------------------------------------------------------------------------
extern "C" void kernel_launch(void* const* d_in, const int* in_sizes, int n_in,
                              void* d_out, int out_size)
{
    const float* x     = (const float*)d_in[0];
    const float* w_qkv = (const float*)d_in[1];
    const float* b_qkv = (const float*)d_in[2];
    const float* w_o   = (const float*)d_in[3];
    const float* b_o   = (const float*)d_in[4];
    float* out = (float*)d_out;

    float* qkv;
    __nv_bfloat16 *xh, *xl, *wqh, *wql, *woh, *wol, *ath, *atl;
    __nv_bfloat16 *pqh, *pql, *pkh, *pkl, *pvh, *pvl;
    cudaGetSymbolAddress((void**)&qkv, g_qkv);
    cudaGetSymbolAddress((void**)&xh,  g_x_hi);  cudaGetSymbolAddress((void**)&xl,  g_x_lo);
    cudaGetSymbolAddress((void**)&wqh, g_wq_hi); cudaGetSymbolAddress((void**)&wql, g_wq_lo);
    cudaGetSymbolAddress((void**)&woh, g_wo_hi); cudaGetSymbolAddress((void**)&wol, g_wo_lo);
    cudaGetSymbolAddress((void**)&ath, g_at_hi); cudaGetSymbolAddress((void**)&atl, g_at_lo);
    cudaGetSymbolAddress((void**)&pqh, g_q_hi);  cudaGetSymbolAddress((void**)&pql, g_q_lo);
    cudaGetSymbolAddress((void**)&pkh, g_k_hi);  cudaGetSymbolAddress((void**)&pkl, g_k_lo);
    cudaGetSymbolAddress((void**)&pvh, g_vt_hi); cudaGetSymbolAddress((void**)&pvl, g_vt_lo);

    cudaFuncSetAttribute(gemm_hmma, cudaFuncAttributeMaxDynamicSharedMemorySize, GEMM_SMEM);
    cudaFuncSetAttribute(attn_mma,  cudaFuncAttributeMaxDynamicSharedMemorySize, ATTN_SMEM);

    // input splits
    {
        int n4 = M_ROWS * KDIM / 4;
        split_kernel<<<(n4 + 255) / 256, 256>>>((const float4*)x,
            (__nv_bfloat162*)xh, (__nv_bfloat162*)xl, n4);
    }
    {
        int n4 = TDQ * KDIM / 4;
        split_kernel<<<(n4 + 255) / 256, 256>>>((const float4*)w_qkv,
            (__nv_bfloat162*)wqh, (__nv_bfloat162*)wql, n4);
    }
    {
        int n4 = D_MODEL * KDIM / 4;
        split_kernel<<<(n4 + 255) / 256, 256>>>((const float4*)w_o,
            (__nv_bfloat162*)woh, (__nv_bfloat162*)wol, n4);
    }

    // 1) QKV projection
    {
        dim3 grid(TDQ / 128, M_ROWS / 128);
        gemm_hmma<<<grid, 256, GEMM_SMEM>>>(xh, xl, wqh, wql, b_qkv, qkv,
                                            M_ROWS, TDQ, KDIM);
    }
    // 2) prep attention planes
    {
        dim3 grid(S_LEN / 256, BH);
        prep_qkv<<<grid, 256>>>(qkv, pqh, pql, pkh, pkl, pvh, pvl);
    }
    // 3) tensor-core flash attention
    {
        dim3 grid(S_LEN / 128, BH);
        attn_mma<<<grid, 256, ATTN_SMEM>>>(pqh, pql, pkh, pkl, pvh, pvl, ath, atl);
    }
    // 4) output projection
    {
        dim3 grid(D_MODEL / 128, M_ROWS / 128);
        gemm_hmma<<<grid, 256, GEMM_SMEM>>>(ath, atl, woh, wol, b_o, out,
                                            M_ROWS, D_MODEL, KDIM);
    }
}

// round 5
// speedup vs baseline: 3.1559x; 1.1459x over previous
#include <cuda_runtime.h>
#include <cuda_bf16.h>
#include <cuda_fp16.h>
#include <cstdint>
#include <cstddef>

// Problem constants
#define BATCH   4
#define S_LEN   2048
#define D_MODEL 1024
#define NHEAD   16
#define HEAD_D  64
#define TDQ     (3 * D_MODEL)          // 3072
#define M_ROWS  (BATCH * S_LEN)        // 8192
#define KDIM    D_MODEL                // 1024
#define BH      (BATCH * NHEAD)        // 64

// ---------------------------------------------------------------------------
// Scratch (__device__ globals; allocation-free rule)
// ---------------------------------------------------------------------------
__device__ __align__(128) float         g_qkv   [(size_t)M_ROWS * TDQ];
__device__ __align__(128) __nv_bfloat16 g_x_hi  [(size_t)M_ROWS * KDIM];
__device__ __align__(128) __nv_bfloat16 g_x_lo  [(size_t)M_ROWS * KDIM];
__device__ __align__(128) __nv_bfloat16 g_wq_hi [(size_t)TDQ    * KDIM];
__device__ __align__(128) __nv_bfloat16 g_wq_lo [(size_t)TDQ    * KDIM];
__device__ __align__(128) __nv_bfloat16 g_wo_hi [(size_t)D_MODEL* KDIM];
__device__ __align__(128) __nv_bfloat16 g_wo_lo [(size_t)D_MODEL* KDIM];
__device__ __align__(128) __nv_bfloat16 g_at_hi [(size_t)M_ROWS * D_MODEL];
__device__ __align__(128) __nv_bfloat16 g_at_lo [(size_t)M_ROWS * D_MODEL];
// attention-ready planes
__device__ __align__(128) __nv_bfloat16 g_q_hi  [(size_t)BH * S_LEN * HEAD_D];
__device__ __align__(128) __nv_bfloat16 g_q_lo  [(size_t)BH * S_LEN * HEAD_D];
__device__ __align__(128) __nv_bfloat16 g_k_hi  [(size_t)BH * S_LEN * HEAD_D];
__device__ __align__(128) __nv_bfloat16 g_k_lo  [(size_t)BH * S_LEN * HEAD_D];
__device__ __align__(128) __half        g_vt    [(size_t)BH * HEAD_D * S_LEN];

// ---------------------------------------------------------------------------
// Helpers
// ---------------------------------------------------------------------------
__device__ __forceinline__ uint32_t smem_u32(const void* p) {
    uint32_t a;
    asm("{ .reg .u64 t; cvta.to.shared.u64 t, %1; cvt.u32.u64 %0, t; }"
        : "=r"(a) : "l"(p));
    return a;
}

#define CP_ASYNC16(saddr, gptr) \
    asm volatile("cp.async.cg.shared.global [%0], [%1], 16;" :: "r"(saddr), "l"(gptr))
#define CP_COMMIT() asm volatile("cp.async.commit_group;" ::: "memory")
#define CP_WAIT0()  asm volatile("cp.async.wait_group 0;" ::: "memory")

__device__ __forceinline__ void ldsm4(uint32_t* r, uint32_t addr) {
    asm volatile("ldmatrix.sync.aligned.m8n8.x4.shared.b16 {%0,%1,%2,%3}, [%4];"
                 : "=r"(r[0]), "=r"(r[1]), "=r"(r[2]), "=r"(r[3]) : "r"(addr));
}
__device__ __forceinline__ void ldsm2(uint32_t* r, uint32_t addr) {
    asm volatile("ldmatrix.sync.aligned.m8n8.x2.shared.b16 {%0,%1}, [%2];"
                 : "=r"(r[0]), "=r"(r[1]) : "r"(addr));
}
__device__ __forceinline__ void mma16816(float* d, const uint32_t* a, const uint32_t* b) {
    asm volatile(
        "mma.sync.aligned.m16n8k16.row.col.f32.bf16.bf16.f32 "
        "{%0,%1,%2,%3}, {%4,%5,%6,%7}, {%8,%9}, {%0,%1,%2,%3};"
        : "+f"(d[0]), "+f"(d[1]), "+f"(d[2]), "+f"(d[3])
        : "r"(a[0]), "r"(a[1]), "r"(a[2]), "r"(a[3]), "r"(b[0]), "r"(b[1]));
}
__device__ __forceinline__ void mma16816h(float* d, const uint32_t* a, const uint32_t* b) {
    asm volatile(
        "mma.sync.aligned.m16n8k16.row.col.f32.f16.f16.f32 "
        "{%0,%1,%2,%3}, {%4,%5,%6,%7}, {%8,%9}, {%0,%1,%2,%3};"
        : "+f"(d[0]), "+f"(d[1]), "+f"(d[2]), "+f"(d[3])
        : "r"(a[0]), "r"(a[1]), "r"(a[2]), "r"(a[3]), "r"(b[0]), "r"(b[1]));
}

__device__ __forceinline__ void split1(float x, __nv_bfloat16& h, __nv_bfloat16& l) {
    h = __float2bfloat16(x);
    l = __float2bfloat16(x - __bfloat162float(h));
}
__device__ __forceinline__ void split2_pack(float x, float y, uint32_t& hi, uint32_t& lo) {
    __nv_bfloat16 hx, lx, hy, ly;
    split1(x, hx, lx); split1(y, hy, ly);
    __nv_bfloat162 th(hx, hy), tl(lx, ly);
    hi = *(uint32_t*)&th; lo = *(uint32_t*)&tl;
}
__device__ __forceinline__ uint32_t pack_h2(float x, float y) {
    __half2 h = __floats2half2_rn(x, y);
    return *(uint32_t*)&h;
}

// ---------------------------------------------------------------------------
// fp32 -> (bf16 hi, bf16 lo) split
// ---------------------------------------------------------------------------
__global__ void __launch_bounds__(256)
split_kernel(const float4* __restrict__ src, __nv_bfloat162* __restrict__ hi,
             __nv_bfloat162* __restrict__ lo, int n4)
{
    int i = blockIdx.x * blockDim.x + threadIdx.x;
    if (i >= n4) return;
    float4 v = src[i];
    __nv_bfloat16 hx, lx, hy, ly, hz, lz, hw, lw;
    split1(v.x, hx, lx); split1(v.y, hy, ly);
    split1(v.z, hz, lz); split1(v.w, hw, lw);
    hi[2 * i + 0] = __nv_bfloat162(hx, hy);
    hi[2 * i + 1] = __nv_bfloat162(hz, hw);
    lo[2 * i + 0] = __nv_bfloat162(lx, ly);
    lo[2 * i + 1] = __nv_bfloat162(lz, lw);
}

// ---------------------------------------------------------------------------
// Split-bf16 HMMA GEMM (NT): 128(M) x 256(N) CTA tile, BK=32, 8 warps as
// 2(M) x 4(N), 64x64 warp tile. cp.async double buffer.
// ---------------------------------------------------------------------------
#define ROWB   80
#define A_ARR  (128 * ROWB)             // 10240
#define B_ARR  (256 * ROWB)             // 20480
#define STAGE_B (2 * A_ARR + 2 * B_ARR) // 61440
#define GEMM_SMEM (2 * STAGE_B)         // 122880

__global__ void __launch_bounds__(256, 1)
gemm_hmma(const __nv_bfloat16* __restrict__ Ahi, const __nv_bfloat16* __restrict__ Alo,
          const __nv_bfloat16* __restrict__ Bhi, const __nv_bfloat16* __restrict__ Blo,
          const float* __restrict__ bias, float* __restrict__ C,
          int M, int N, int K)
{
    extern __shared__ char sm[];
    const int tid  = threadIdx.x;
    const int wid  = tid >> 5;
    const int lane = tid & 31;
    const int wm   = wid & 1;           // 0..1 (M)
    const int wn   = wid >> 1;          // 0..3 (N)
    const int row0 = blockIdx.y * 128;
    const int col0 = blockIdx.x * 256;

    const uint32_t smb = smem_u32(sm);
    const int lr = tid >> 2;            // 0..63
    const int lc = tid & 3;             // 16B chunk

    auto ld_chunk = [&](int i, int stage) {
        const int k0 = i * 32;
        uint32_t sb = smb + stage * STAGE_B;
        #pragma unroll
        for (int rep = 0; rep < 2; rep++) {
            int rr = lr + rep * 64;
            size_t go = (size_t)(row0 + rr) * K + k0 + lc * 8;
            uint32_t so = rr * ROWB + lc * 16;
            CP_ASYNC16(sb +         so, Ahi + go);
            CP_ASYNC16(sb + A_ARR + so, Alo + go);
        }
        #pragma unroll
        for (int rep = 0; rep < 4; rep++) {
            int rr = lr + rep * 64;
            size_t go = (size_t)(col0 + rr) * K + k0 + lc * 8;
            uint32_t so = rr * ROWB + lc * 16;
            CP_ASYNC16(sb + 2 * A_ARR +         so, Bhi + go);
            CP_ASYNC16(sb + 2 * A_ARR + B_ARR + so, Blo + go);
        }
    };

    float acc[4][8][4];
    #pragma unroll
    for (int i = 0; i < 4; i++)
        #pragma unroll
        for (int j = 0; j < 8; j++)
            #pragma unroll
            for (int v = 0; v < 4; v++) acc[i][j][v] = 0.f;

    const int arow = (lane & 7) + ((lane >> 3) & 1) * 8;
    const int akb  = (lane >> 4) * 16;
    const uint32_t aoff = (uint32_t)((wm * 64 + arow) * ROWB + akb);
    const uint32_t boff = (uint32_t)((wn * 64 + (lane & 7)) * ROWB + ((lane >> 3) & 1) * 16);

    const int NC = K / 32;
    ld_chunk(0, 0);
    CP_COMMIT();
    CP_WAIT0();
    __syncthreads();

    for (int i = 0; i < NC; i++) {
        const int st = i & 1;
        if (i + 1 < NC) { ld_chunk(i + 1, st ^ 1); CP_COMMIT(); }

        const uint32_t sA  = smb + st * STAGE_B;
        const uint32_t sAl = sA + A_ARR;
        const uint32_t sB  = sA + 2 * A_ARR;
        const uint32_t sBl = sB + B_ARR;

        #pragma unroll
        for (int ks = 0; ks < 2; ks++) {
            uint32_t ah[4][4], al[4][4], bh[8][2], bl[8][2];
            #pragma unroll
            for (int fi = 0; fi < 4; fi++) {
                ldsm4(ah[fi], sA  + aoff + fi * 16 * ROWB + ks * 32);
                ldsm4(al[fi], sAl + aoff + fi * 16 * ROWB + ks * 32);
            }
            #pragma unroll
            for (int fj = 0; fj < 8; fj++) {
                ldsm2(bh[fj], sB  + boff + fj * 8 * ROWB + ks * 32);
                ldsm2(bl[fj], sBl + boff + fj * 8 * ROWB + ks * 32);
            }
            #pragma unroll
            for (int fi = 0; fi < 4; fi++)
                #pragma unroll
                for (int fj = 0; fj < 8; fj++) {
                    mma16816(acc[fi][fj], ah[fi], bh[fj]);
                    mma16816(acc[fi][fj], ah[fi], bl[fj]);
                    mma16816(acc[fi][fj], al[fi], bh[fj]);
                }
        }
        if (i + 1 < NC) CP_WAIT0();
        __syncthreads();
    }

    #pragma unroll
    for (int fi = 0; fi < 4; fi++) {
        const int r = row0 + wm * 64 + fi * 16 + (lane >> 2);
        #pragma unroll
        for (int fj = 0; fj < 8; fj++) {
            const int cc = col0 + wn * 64 + fj * 8 + (lane & 3) * 2;
            float2 bb = *(const float2*)&bias[cc];
            float2 v0 = make_float2(acc[fi][fj][0] + bb.x, acc[fi][fj][1] + bb.y);
            float2 v1 = make_float2(acc[fi][fj][2] + bb.x, acc[fi][fj][3] + bb.y);
            *(float2*)&C[(size_t)r * N + cc]       = v0;
            *(float2*)&C[(size_t)(r + 8) * N + cc] = v1;
        }
    }
}

// ---------------------------------------------------------------------------
// Prep: qkv fp32 -> Q/K bf16 hi+lo planes [bh][s][64] (Q scaled 1/8),
//       V^T fp16 plane [bh][d][s].
// ---------------------------------------------------------------------------
__global__ void __launch_bounds__(256)
prep_qkv(const float* __restrict__ qkv,
         __nv_bfloat16* __restrict__ qh, __nv_bfloat16* __restrict__ ql,
         __nv_bfloat16* __restrict__ kh, __nv_bfloat16* __restrict__ kl,
         __half* __restrict__ vt)
{
    const int s  = blockIdx.x * 256 + threadIdx.x;
    const int bh = blockIdx.y;
    const int b  = bh >> 4;
    const int h  = bh & 15;
    const float* src = qkv + ((size_t)(b * S_LEN + s)) * TDQ + h * 3 * HEAD_D;

    __nv_bfloat16* qhp = qh + ((size_t)bh * S_LEN + s) * HEAD_D;
    __nv_bfloat16* qlp = ql + ((size_t)bh * S_LEN + s) * HEAD_D;
    __nv_bfloat16* khp = kh + ((size_t)bh * S_LEN + s) * HEAD_D;
    __nv_bfloat16* klp = kl + ((size_t)bh * S_LEN + s) * HEAD_D;

    #pragma unroll
    for (int j = 0; j < 16; j++) {
        float4 qv = *(const float4*)(src + 4 * j);
        float4 kv = *(const float4*)(src + HEAD_D + 4 * j);
        __nv_bfloat16 hh, ll;
        split1(qv.x * 0.125f, hh, ll); qhp[4*j+0] = hh; qlp[4*j+0] = ll;
        split1(qv.y * 0.125f, hh, ll); qhp[4*j+1] = hh; qlp[4*j+1] = ll;
        split1(qv.z * 0.125f, hh, ll); qhp[4*j+2] = hh; qlp[4*j+2] = ll;
        split1(qv.w * 0.125f, hh, ll); qhp[4*j+3] = hh; qlp[4*j+3] = ll;
        split1(kv.x, hh, ll); khp[4*j+0] = hh; klp[4*j+0] = ll;
        split1(kv.y, hh, ll); khp[4*j+1] = hh; klp[4*j+1] = ll;
        split1(kv.z, hh, ll); khp[4*j+2] = hh; klp[4*j+2] = ll;
        split1(kv.w, hh, ll); khp[4*j+3] = hh; klp[4*j+3] = ll;
    }
    #pragma unroll
    for (int j = 0; j < 16; j++) {
        float4 vv = *(const float4*)(src + 2 * HEAD_D + 4 * j);
        #pragma unroll
        for (int e = 0; e < 4; e++) {
            float val = (e == 0) ? vv.x : (e == 1) ? vv.y : (e == 2) ? vv.z : vv.w;
            int d = 4 * j + e;
            vt[((size_t)bh * HEAD_D + d) * S_LEN + s] = __float2half(val);
        }
    }
}

// ---------------------------------------------------------------------------
// Flash attention on HMMA. 128 q rows/CTA, 8 warps x 16 rows, 64-key tiles.
// QK^T: 3-pass bf16 split. PV: single-pass fp16 (P and V in fp16).
// ---------------------------------------------------------------------------
#define AROW     144
#define Q_ARR    (128 * AROW)          // 18432
#define T_ARR    (64 * AROW)           // 9216
#define T_STAGE  (3 * T_ARR)           // 27648 (Kh, Kl, V)
#define ATTN_SMEM (2 * Q_ARR + 2 * T_STAGE)   // 92160

__global__ void __launch_bounds__(256, 1)
attn_mma(const __nv_bfloat16* __restrict__ qh, const __nv_bfloat16* __restrict__ ql,
         const __nv_bfloat16* __restrict__ kh, const __nv_bfloat16* __restrict__ kl,
         const __half* __restrict__ vt,
         __nv_bfloat16* __restrict__ outh, __nv_bfloat16* __restrict__ outl)
{
    extern __shared__ char sm[];
    const uint32_t smb = smem_u32(sm);
    const int tid  = threadIdx.x;
    const int wid  = tid >> 5;
    const int lane = tid & 31;
    const int bh = blockIdx.y;
    const int qb = blockIdx.x;

    const __nv_bfloat16* Qh = qh + ((size_t)bh * S_LEN + qb * 128) * HEAD_D;
    const __nv_bfloat16* Ql = ql + ((size_t)bh * S_LEN + qb * 128) * HEAD_D;
    const __nv_bfloat16* Kh = kh + (size_t)bh * S_LEN * HEAD_D;
    const __nv_bfloat16* Kl = kl + (size_t)bh * S_LEN * HEAD_D;
    const __half*        Vt = vt + (size_t)bh * HEAD_D * S_LEN;

    auto ld_tile = [&](int kt, int st) {
        const int k0 = kt * 64;
        const uint32_t sb = smb + 2 * Q_ARR + st * T_STAGE;
        #pragma unroll
        for (int rep = 0; rep < 2; rep++) {
            int idx = tid + rep * 256;        // 0..511
            int row = idx >> 3;               // 0..63
            int ch  = idx & 7;
            uint32_t so = row * AROW + ch * 16;
            CP_ASYNC16(sb +             so, Kh + (size_t)(k0 + row) * HEAD_D + ch * 8);
            CP_ASYNC16(sb + T_ARR +     so, Kl + (size_t)(k0 + row) * HEAD_D + ch * 8);
            CP_ASYNC16(sb + 2 * T_ARR + so, Vt + (size_t)row * S_LEN + k0 + ch * 8);
        }
    };

    #pragma unroll
    for (int rep = 0; rep < 4; rep++) {
        int idx = tid + rep * 256;
        int row = idx >> 3;
        int ch  = idx & 7;
        uint32_t so = row * AROW + ch * 16;
        CP_ASYNC16(smb +         so, Qh + (size_t)row * HEAD_D + ch * 8);
        CP_ASYNC16(smb + Q_ARR + so, Ql + (size_t)row * HEAD_D + ch * 8);
    }
    ld_tile(0, 0);
    CP_COMMIT();
    CP_WAIT0();
    __syncthreads();

    const int arow = (lane & 7) + ((lane >> 3) & 1) * 8;
    const int akb  = (lane >> 4) * 16;
    const uint32_t qbase = smb + (uint32_t)((wid * 16 + arow) * AROW + akb);
    uint32_t qfh[4][4], qfl[4][4];
    #pragma unroll
    for (int kk = 0; kk < 4; kk++) {
        ldsm4(qfh[kk], qbase + kk * 32);
        ldsm4(qfl[kk], qbase + Q_ARR + kk * 32);
    }

    float o[8][4];
    #pragma unroll
    for (int nf = 0; nf < 8; nf++)
        #pragma unroll
        for (int v = 0; v < 4; v++) o[nf][v] = 0.f;
    float m0 = -1e30f, m1 = -1e30f, l0 = 0.f, l1 = 0.f;

    const uint32_t bo = (uint32_t)((lane & 7) * AROW + ((lane >> 3) & 1) * 16);
    const int NT = S_LEN / 64;

    for (int kt = 0; kt < NT; kt++) {
        const int st = kt & 1;
        if (kt + 1 < NT) { ld_tile(kt + 1, st ^ 1); CP_COMMIT(); }

        const uint32_t base_k = smb + 2 * Q_ARR + st * T_STAGE;
        const uint32_t base_v = base_k + 2 * T_ARR;

        float s_[8][4];
        #pragma unroll
        for (int nf = 0; nf < 8; nf++)
            #pragma unroll
            for (int v = 0; v < 4; v++) s_[nf][v] = 0.f;

        #pragma unroll
        for (int nf = 0; nf < 8; nf++) {
            #pragma unroll
            for (int kk = 0; kk < 4; kk++) {
                uint32_t addr = base_k + bo + nf * 8 * AROW + kk * 32;
                uint32_t kbh[2], kbl[2];
                ldsm2(kbh, addr);
                ldsm2(kbl, addr + T_ARR);
                mma16816(s_[nf], qfh[kk], kbh);
                mma16816(s_[nf], qfh[kk], kbl);
                mma16816(s_[nf], qfl[kk], kbh);
            }
        }

        float tm0 = -1e30f, tm1 = -1e30f;
        #pragma unroll
        for (int nf = 0; nf < 8; nf++) {
            tm0 = fmaxf(tm0, fmaxf(s_[nf][0], s_[nf][1]));
            tm1 = fmaxf(tm1, fmaxf(s_[nf][2], s_[nf][3]));
        }
        tm0 = fmaxf(tm0, __shfl_xor_sync(0xffffffffu, tm0, 1));
        tm0 = fmaxf(tm0, __shfl_xor_sync(0xffffffffu, tm0, 2));
        tm1 = fmaxf(tm1, __shfl_xor_sync(0xffffffffu, tm1, 1));
        tm1 = fmaxf(tm1, __shfl_xor_sync(0xffffffffu, tm1, 2));

        const float mn0 = fmaxf(m0, tm0);
        const float mn1 = fmaxf(m1, tm1);
        const float a0 = __expf(m0 - mn0);
        const float a1 = __expf(m1 - mn1);
        m0 = mn0; m1 = mn1;

        float sum0 = 0.f, sum1 = 0.f;
        #pragma unroll
        for (int nf = 0; nf < 8; nf++) {
            s_[nf][0] = __expf(s_[nf][0] - m0);
            s_[nf][1] = __expf(s_[nf][1] - m0);
            s_[nf][2] = __expf(s_[nf][2] - m1);
            s_[nf][3] = __expf(s_[nf][3] - m1);
            sum0 += s_[nf][0] + s_[nf][1];
            sum1 += s_[nf][2] + s_[nf][3];
        }
        sum0 += __shfl_xor_sync(0xffffffffu, sum0, 1);
        sum0 += __shfl_xor_sync(0xffffffffu, sum0, 2);
        sum1 += __shfl_xor_sync(0xffffffffu, sum1, 1);
        sum1 += __shfl_xor_sync(0xffffffffu, sum1, 2);
        l0 = l0 * a0 + sum0;
        l1 = l1 * a1 + sum1;

        #pragma unroll
        for (int nf = 0; nf < 8; nf++) {
            o[nf][0] *= a0; o[nf][1] *= a0;
            o[nf][2] *= a1; o[nf][3] *= a1;
        }

        // P -> fp16 A fragments (single pass)
        uint32_t pa[4][4];
        #pragma unroll
        for (int kk = 0; kk < 4; kk++) {
            const int n0 = 2 * kk, n1 = 2 * kk + 1;
            pa[kk][0] = pack_h2(s_[n0][0], s_[n0][1]);
            pa[kk][1] = pack_h2(s_[n0][2], s_[n0][3]);
            pa[kk][2] = pack_h2(s_[n1][0], s_[n1][1]);
            pa[kk][3] = pack_h2(s_[n1][2], s_[n1][3]);
        }

        // O += P V (1 pass fp16); B = V^T tile [dim][key]
        #pragma unroll
        for (int nf = 0; nf < 8; nf++) {
            #pragma unroll
            for (int kk = 0; kk < 4; kk++) {
                uint32_t vb[2];
                ldsm2(vb, base_v + bo + nf * 8 * AROW + kk * 32);
                mma16816h(o[nf], pa[kk], vb);
            }
        }

        if (kt + 1 < NT) CP_WAIT0();
        __syncthreads();
    }

    const float inv0 = 1.f / l0;
    const float inv1 = 1.f / l1;
    const int b = bh >> 4;
    const int h = bh & 15;
    const int r0 = qb * 128 + wid * 16 + (lane >> 2);
    const size_t tok0 = (size_t)(b * S_LEN + r0) * D_MODEL;
    const size_t tok1 = (size_t)(b * S_LEN + r0 + 8) * D_MODEL;
    #pragma unroll
    for (int nf = 0; nf < 8; nf++) {
        const int col = h * HEAD_D + nf * 8 + (lane & 3) * 2;
        uint32_t hi, lo;
        split2_pack(o[nf][0] * inv0, o[nf][1] * inv0, hi, lo);
        *(uint32_t*)(outh + tok0 + col) = hi;
        *(uint32_t*)(outl + tok0 + col) = lo;
        split2_pack(o[nf][2] * inv1, o[nf][3] * inv1, hi, lo);
        *(uint32_t*)(outh + tok1 + col) = hi;
        *(uint32_t*)(outl + tok1 + col) = lo;
    }
}

// ---------------------------------------------------------------------------
extern "C" void kernel_launch(void* const* d_in, const int* in_sizes, int n_in,
                              void* d_out, int out_size)
{
    const float* x     = (const float*)d_in[0];
    const float* w_qkv = (const float*)d_in[1];
    const float* b_qkv = (const float*)d_in[2];
    const float* w_o   = (const float*)d_in[3];
    const float* b_o   = (const float*)d_in[4];
    float* out = (float*)d_out;

    float* qkv;
    __nv_bfloat16 *xh, *xl, *wqh, *wql, *woh, *wol, *ath, *atl;
    __nv_bfloat16 *pqh, *pql, *pkh, *pkl;
    __half* pvt;
    cudaGetSymbolAddress((void**)&qkv, g_qkv);
    cudaGetSymbolAddress((void**)&xh,  g_x_hi);  cudaGetSymbolAddress((void**)&xl,  g_x_lo);
    cudaGetSymbolAddress((void**)&wqh, g_wq_hi); cudaGetSymbolAddress((void**)&wql, g_wq_lo);
    cudaGetSymbolAddress((void**)&woh, g_wo_hi); cudaGetSymbolAddress((void**)&wol, g_wo_lo);
    cudaGetSymbolAddress((void**)&ath, g_at_hi); cudaGetSymbolAddress((void**)&atl, g_at_lo);
    cudaGetSymbolAddress((void**)&pqh, g_q_hi);  cudaGetSymbolAddress((void**)&pql, g_q_lo);
    cudaGetSymbolAddress((void**)&pkh, g_k_hi);  cudaGetSymbolAddress((void**)&pkl, g_k_lo);
    cudaGetSymbolAddress((void**)&pvt, g_vt);

    cudaFuncSetAttribute(gemm_hmma, cudaFuncAttributeMaxDynamicSharedMemorySize, GEMM_SMEM);
    cudaFuncSetAttribute(attn_mma,  cudaFuncAttributeMaxDynamicSharedMemorySize, ATTN_SMEM);

    // input splits
    {
        int n4 = M_ROWS * KDIM / 4;
        split_kernel<<<(n4 + 255) / 256, 256>>>((const float4*)x,
            (__nv_bfloat162*)xh, (__nv_bfloat162*)xl, n4);
    }
    {
        int n4 = TDQ * KDIM / 4;
        split_kernel<<<(n4 + 255) / 256, 256>>>((const float4*)w_qkv,
            (__nv_bfloat162*)wqh, (__nv_bfloat162*)wql, n4);
    }
    {
        int n4 = D_MODEL * KDIM / 4;
        split_kernel<<<(n4 + 255) / 256, 256>>>((const float4*)w_o,
            (__nv_bfloat162*)woh, (__nv_bfloat162*)wol, n4);
    }

    // 1) QKV projection
    {
        dim3 grid(TDQ / 256, M_ROWS / 128);
        gemm_hmma<<<grid, 256, GEMM_SMEM>>>(xh, xl, wqh, wql, b_qkv, qkv,
                                            M_ROWS, TDQ, KDIM);
    }
    // 2) prep attention planes
    {
        dim3 grid(S_LEN / 256, BH);
        prep_qkv<<<grid, 256>>>(qkv, pqh, pql, pkh, pkl, pvt);
    }
    // 3) tensor-core flash attention
    {
        dim3 grid(S_LEN / 128, BH);
        attn_mma<<<grid, 256, ATTN_SMEM>>>(pqh, pql, pkh, pkl, pvt, ath, atl);
    }
    // 4) output projection
    {
        dim3 grid(D_MODEL / 256, M_ROWS / 128);
        gemm_hmma<<<grid, 256, GEMM_SMEM>>>(ath, atl, woh, wol, b_o, out,
                                            M_ROWS, D_MODEL, KDIM);
    }
}